// round 3
// baseline (speedup 1.0000x reference)
#include <cuda_runtime.h>
#include <cstdint>

// Problem constants (fixed by the dataset)
#define NN   100000       // nodes
#define NE   1600000      // edges (excluding self loops)
#define FD   128          // feature / hidden dim
#define NC   64           // classes
#define NB_SCAN 98        // ceil(NN / 1024)

// ---------------- scratch (device globals; no allocation allowed) ----------
__device__ float g_buf1[NN * FD];   // GEMM output h
__device__ float g_buf2[NN * FD];   // aggregation output
__device__ float g_buf3[NN * FD];   // activation
__device__ float g_dinv[NN];
__device__ int   g_deg[NN];         // in-degree (without self loop)
__device__ int   g_rowstart[NN];    // exclusive prefix of deg
__device__ int   g_cursor[NN];
__device__ int   g_csrc[NE];        // src node per incoming edge, grouped by dst
__device__ float g_cnorm[NE];       // dinv[src]*dinv[dst] per incoming edge
__device__ int   g_bsum[128];
__device__ int   g_boff[128];

// ---------------- preprocessing kernels ------------------------------------

__global__ void k_init()
{
    int i = blockIdx.x * blockDim.x + threadIdx.x;
    if (i < NN) { g_deg[i] = 0; g_cursor[i] = 0; }
}

__global__ void k_count(const int* __restrict__ ei)
{
    int e = blockIdx.x * blockDim.x + threadIdx.x;
    if (e < NE) {
        int d = ei[NE + e];
        atomicAdd(&g_deg[d], 1);
    }
}

__global__ void k_scan_blocks()
{
    __shared__ int s[1024];
    int t = threadIdx.x;
    int i = blockIdx.x * 1024 + t;
    int v = (i < NN) ? g_deg[i] : 0;
    s[t] = v;
    __syncthreads();
    #pragma unroll
    for (int off = 1; off < 1024; off <<= 1) {
        int add = (t >= off) ? s[t - off] : 0;
        __syncthreads();
        s[t] += add;
        __syncthreads();
    }
    if (i < NN) g_rowstart[i] = s[t] - v;          // exclusive within block
    if (t == 1023) g_bsum[blockIdx.x] = s[t];      // block total
}

__global__ void k_scan_top()
{
    __shared__ int s[128];
    int t = threadIdx.x;
    int v = (t < NB_SCAN) ? g_bsum[t] : 0;
    s[t] = v;
    __syncthreads();
    #pragma unroll
    for (int off = 1; off < 128; off <<= 1) {
        int add = (t >= off) ? s[t - off] : 0;
        __syncthreads();
        s[t] += add;
        __syncthreads();
    }
    g_boff[t] = s[t] - v;                          // exclusive block offsets
}

__global__ void k_finish()
{
    int i = blockIdx.x * blockDim.x + threadIdx.x;
    if (i < NN) {
        g_rowstart[i] += g_boff[i >> 10];
        g_dinv[i] = rsqrtf((float)g_deg[i] + 1.0f);   // +1 = self loop
    }
}

__global__ void k_fill(const int* __restrict__ ei)
{
    int e = blockIdx.x * blockDim.x + threadIdx.x;
    if (e < NE) {
        int s = ei[e];
        int d = ei[NE + e];
        int p = g_rowstart[d] + atomicAdd(&g_cursor[d], 1);
        g_csrc[p]  = s;
        g_cnorm[p] = g_dinv[s] * g_dinv[d];
    }
}

// ---------------- GEMM: C[NN, OUT] = A[NN,128] @ W[OUT,128]^T (+bias) ------
// TILE_M = 128 rows per block, full K=128 in smem, 256 threads,
// per-thread micro-tile: 8 rows x (OUT/16) cols.
template <int OUT>
__global__ void __launch_bounds__(256) k_gemm(
    const float* __restrict__ A, const float* __restrict__ W,
    const float* __restrict__ bias, float* __restrict__ C)
{
    extern __shared__ float sm[];
    const int WS = OUT + 4;                // padded stride for Wt
    float* Wt = sm;                        // [128][WS]   Wt[k][j] = W[j][k]
    float* Xs = sm + 128 * WS;             // [128][132]
    const int tid = threadIdx.x;

    for (int idx = tid; idx < OUT * 128; idx += 256) {
        int j = idx >> 7, k = idx & 127;
        Wt[k * WS + j] = W[idx];
    }
    const int row0 = blockIdx.x * 128;
    for (int idx = tid; idx < 128 * 32; idx += 256) {
        int r = idx >> 5, c4 = idx & 31;
        float4 v = make_float4(0.f, 0.f, 0.f, 0.f);
        if (row0 + r < NN)
            v = reinterpret_cast<const float4*>(A)[(size_t)(row0 + r) * 32 + c4];
        *reinterpret_cast<float4*>(&Xs[r * 132 + c4 * 4]) = v;
    }
    __syncthreads();

    const int tm = tid >> 4;               // 0..15 -> rows tm*8 .. tm*8+7
    const int tc = tid & 15;               // cols tc*JC .. tc*JC+JC-1
    const int JC = OUT / 16;               // 8 or 4

    float acc[8][JC];
    #pragma unroll
    for (int i = 0; i < 8; i++)
        #pragma unroll
        for (int j = 0; j < JC; j++) acc[i][j] = 0.f;

    #pragma unroll 4
    for (int k = 0; k < 128; ++k) {
        float a[8], b[JC];
        #pragma unroll
        for (int i = 0; i < 8; i++) a[i] = Xs[(tm * 8 + i) * 132 + k];
        #pragma unroll
        for (int j = 0; j < JC; j++) b[j] = Wt[k * WS + tc * JC + j];
        #pragma unroll
        for (int i = 0; i < 8; i++)
            #pragma unroll
            for (int j = 0; j < JC; j++) acc[i][j] += a[i] * b[j];
    }

    #pragma unroll
    for (int i = 0; i < 8; i++) {
        int r = row0 + tm * 8 + i;
        if (r < NN) {
            #pragma unroll
            for (int j4 = 0; j4 < JC / 4; j4++) {
                int c = tc * JC + j4 * 4;
                float4 v;
                v.x = acc[i][j4 * 4 + 0];
                v.y = acc[i][j4 * 4 + 1];
                v.z = acc[i][j4 * 4 + 2];
                v.w = acc[i][j4 * 4 + 3];
                if (bias) {
                    v.x += __ldg(&bias[c + 0]);
                    v.y += __ldg(&bias[c + 1]);
                    v.z += __ldg(&bias[c + 2]);
                    v.w += __ldg(&bias[c + 3]);
                }
                *reinterpret_cast<float4*>(&C[(size_t)r * OUT + c]) = v;
            }
        }
    }
}

// ---------------- aggregation: pure gather, one warp per node --------------
__global__ void k_agg(const float* __restrict__ h, float* __restrict__ out)
{
    int gw = (blockIdx.x * blockDim.x + threadIdx.x) >> 5;   // node id
    if (gw >= NN) return;
    int lane = threadIdx.x & 31;
    int beg = g_rowstart[gw];
    int cnt = g_deg[gw];
    const float4* hp = reinterpret_cast<const float4*>(h);
    float4 acc = make_float4(0.f, 0.f, 0.f, 0.f);
    for (int t = 0; t < cnt; ++t) {
        int   s  = __ldg(&g_csrc[beg + t]);
        float nm = __ldg(&g_cnorm[beg + t]);
        float4 hv = __ldg(&hp[(size_t)s * 32 + lane]);
        acc.x += nm * hv.x;
        acc.y += nm * hv.y;
        acc.z += nm * hv.z;
        acc.w += nm * hv.w;
    }
    reinterpret_cast<float4*>(out)[(size_t)gw * 32 + lane] = acc;
}

// ---------------- bias + self-loop + ReLU ----------------------------------
__global__ void k_relu(const float* __restrict__ agg, const float* __restrict__ h,
                       const float* __restrict__ bias, float* __restrict__ out)
{
    int i = blockIdx.x * blockDim.x + threadIdx.x;   // over NN*32 float4s
    if (i >= NN * 32) return;
    int node = i >> 5;
    int f4   = i & 31;
    float di = g_dinv[node];
    float c  = di * di;                               // self-loop norm
    float4 a  = reinterpret_cast<const float4*>(agg)[i];
    float4 hv = reinterpret_cast<const float4*>(h)[i];
    float4 b  = reinterpret_cast<const float4*>(bias)[f4];
    float4 r;
    r.x = fmaxf(a.x + c * hv.x + b.x, 0.f);
    r.y = fmaxf(a.y + c * hv.y + b.y, 0.f);
    r.z = fmaxf(a.z + c * hv.z + b.z, 0.f);
    r.w = fmaxf(a.w + c * hv.w + b.w, 0.f);
    reinterpret_cast<float4*>(out)[i] = r;
}

// ---------------- launcher --------------------------------------------------
extern "C" void kernel_launch(void* const* d_in, const int* in_sizes, int n_in,
                              void* d_out, int out_size)
{
    (void)in_sizes; (void)n_in; (void)out_size;
    const float* x  = (const float*)d_in[0];
    const int*   ei = (const int*)d_in[1];          // int32! (JAX x64 disabled)
    const float* W1 = (const float*)d_in[2];
    const float* b1 = (const float*)d_in[3];
    const float* W2 = (const float*)d_in[4];
    const float* b2 = (const float*)d_in[5];
    const float* Wl = (const float*)d_in[6];
    const float* bl = (const float*)d_in[7];
    float* out = (float*)d_out;

    void *pb1, *pb2, *pb3;
    cudaGetSymbolAddress(&pb1, g_buf1);
    cudaGetSymbolAddress(&pb2, g_buf2);
    cudaGetSymbolAddress(&pb3, g_buf3);
    float* buf1 = (float*)pb1;
    float* buf2 = (float*)pb2;
    float* buf3 = (float*)pb3;

    const int SMEM128 = (128 * (128 + 4) + 128 * 132) * 4;   // 135168 B
    const int SMEM64  = (128 * (64 + 4)  + 128 * 132) * 4;   // 102400 B
    cudaFuncSetAttribute(k_gemm<128>, cudaFuncAttributeMaxDynamicSharedMemorySize, SMEM128);
    cudaFuncSetAttribute(k_gemm<64>,  cudaFuncAttributeMaxDynamicSharedMemorySize, SMEM64);

    const int TB = 256;
    const int GB_N  = (NN + TB - 1) / TB;          // 391
    const int GB_E  = (NE + TB - 1) / TB;          // 6250
    const int GB_W  = (NN * 32 + TB - 1) / TB;     // 12500 (warp/node, float4/relu)
    const int GB_MM = (NN + 127) / 128;            // 782

    // --- graph preprocessing (recomputed every call: deterministic work) ---
    k_init<<<GB_N, TB>>>();
    k_count<<<GB_E, TB>>>(ei);
    k_scan_blocks<<<NB_SCAN, 1024>>>();
    k_scan_top<<<1, 128>>>();
    k_finish<<<GB_N, TB>>>();
    k_fill<<<GB_E, TB>>>(ei);

    // --- layer 1 ---
    k_gemm<128><<<GB_MM, TB, SMEM128>>>(x, W1, nullptr, buf1);
    k_agg<<<GB_W, TB>>>(buf1, buf2);
    k_relu<<<GB_W, TB>>>(buf2, buf1, b1, buf3);

    // --- layer 2 ---
    k_gemm<128><<<GB_MM, TB, SMEM128>>>(buf3, W2, nullptr, buf1);
    k_agg<<<GB_W, TB>>>(buf1, buf2);
    k_relu<<<GB_W, TB>>>(buf2, buf1, b2, buf3);

    // --- readout ---
    k_gemm<64><<<GB_MM, TB, SMEM64>>>(buf3, Wl, bl, out);
}

// round 4
// speedup vs baseline: 1.1255x; 1.1255x over previous
#include <cuda_runtime.h>
#include <cstdint>

// Problem constants (fixed by the dataset)
#define NN   100000       // nodes
#define NE   1600000      // edges (excluding self loops)
#define FD   128          // feature / hidden dim
#define NC   64           // classes
#define NB_SCAN 98        // ceil(NN / 1024)

// ---------------- scratch (device globals; no allocation allowed) ----------
__device__ float g_buf1[NN * FD];   // GEMM output h
__device__ float g_buf3[NN * FD];   // activation (agg+relu output)
__device__ float g_dinv[NN];
__device__ int   g_deg[NN];         // in-degree (without self loop)
__device__ int   g_rowstart[NN];    // exclusive prefix of deg
__device__ int   g_cursor[NN];
__device__ int   g_csrc[NE];        // src node per incoming edge, grouped by dst
__device__ float g_cnorm[NE];       // dinv[src]*dinv[dst] per incoming edge
__device__ int   g_bsum[128];
__device__ int   g_boff[128];

// ---------------- preprocessing kernels ------------------------------------

__global__ void k_init()
{
    int i = blockIdx.x * blockDim.x + threadIdx.x;
    if (i < NN) { g_deg[i] = 0; g_cursor[i] = 0; }
}

__global__ void k_count(const int* __restrict__ ei)
{
    int e = blockIdx.x * blockDim.x + threadIdx.x;
    if (e < NE) {
        int d = ei[NE + e];
        atomicAdd(&g_deg[d], 1);
    }
}

__global__ void k_scan_blocks()
{
    __shared__ int s[1024];
    int t = threadIdx.x;
    int i = blockIdx.x * 1024 + t;
    int v = (i < NN) ? g_deg[i] : 0;
    s[t] = v;
    __syncthreads();
    #pragma unroll
    for (int off = 1; off < 1024; off <<= 1) {
        int add = (t >= off) ? s[t - off] : 0;
        __syncthreads();
        s[t] += add;
        __syncthreads();
    }
    if (i < NN) g_rowstart[i] = s[t] - v;          // exclusive within block
    if (t == 1023) g_bsum[blockIdx.x] = s[t];      // block total
}

__global__ void k_scan_top()
{
    __shared__ int s[128];
    int t = threadIdx.x;
    int v = (t < NB_SCAN) ? g_bsum[t] : 0;
    s[t] = v;
    __syncthreads();
    #pragma unroll
    for (int off = 1; off < 128; off <<= 1) {
        int add = (t >= off) ? s[t - off] : 0;
        __syncthreads();
        s[t] += add;
        __syncthreads();
    }
    g_boff[t] = s[t] - v;                          // exclusive block offsets
}

__global__ void k_finish()
{
    int i = blockIdx.x * blockDim.x + threadIdx.x;
    if (i < NN) {
        g_rowstart[i] += g_boff[i >> 10];
        g_dinv[i] = rsqrtf((float)g_deg[i] + 1.0f);   // +1 = self loop
    }
}

__global__ void k_fill(const int* __restrict__ ei)
{
    int e = blockIdx.x * blockDim.x + threadIdx.x;
    if (e < NE) {
        int s = ei[e];
        int d = ei[NE + e];
        int p = g_rowstart[d] + atomicAdd(&g_cursor[d], 1);
        g_csrc[p]  = s;
        g_cnorm[p] = g_dinv[s] * g_dinv[d];
    }
}

// ---------------- TF32 helpers ---------------------------------------------
__device__ __forceinline__ uint32_t f2tf32(float v)
{
    uint32_t r;
    asm("cvt.rna.tf32.f32 %0, %1;" : "=r"(r) : "f"(v));
    return r;
}

__device__ __forceinline__ void mma_tf32(
    float& d0, float& d1, float& d2, float& d3,
    uint32_t a0, uint32_t a1, uint32_t a2, uint32_t a3,
    uint32_t b0, uint32_t b1)
{
    asm volatile(
        "mma.sync.aligned.m16n8k8.row.col.f32.tf32.tf32.f32 "
        "{%0,%1,%2,%3}, {%4,%5,%6,%7}, {%8,%9}, {%0,%1,%2,%3};"
        : "+f"(d0), "+f"(d1), "+f"(d2), "+f"(d3)
        : "r"(a0), "r"(a1), "r"(a2), "r"(a3), "r"(b0), "r"(b1));
}

// ---------------- GEMM: C[NN, OUT] = A[NN,128] @ W[OUT,128]^T (+bias) ------
// TF32 tensor-core GEMM with 2-term error-compensated split:
//   v = hi + lo (hi = tf32(v), lo = tf32(v - hi))
//   a*b ~= a_lo*b_hi + a_hi*b_lo + a_hi*b_hi       (lo*lo dropped, ~1e-7 rel)
// Block: 256 threads = 8 warps (4 m-warps x 2 n-warps).
// Block tile: 128 x OUT.  Warp tile: 32 x OUT/2 -> 2 m-atoms x OUT/16 n-atoms.
template <int OUT>
__global__ void __launch_bounds__(256) k_gemm(
    const float* __restrict__ A, const float* __restrict__ W,
    const float* __restrict__ bias, float* __restrict__ C)
{
    constexpr int NA = OUT / 16;          // n-atoms per warp (8 or 4)
    extern __shared__ float sm[];
    float* Xs = sm;                        // [128][132]
    float* Ws = sm + 128 * 132;            // [OUT][132]  Ws[j][k] = W[j][k]
    const int tid  = threadIdx.x;
    const int warp = tid >> 5;
    const int lane = tid & 31;

    // load W tile
    for (int idx = tid; idx < OUT * 128; idx += 256) {
        int j = idx >> 7, k = idx & 127;
        Ws[j * 132 + k] = W[idx];
    }
    // load A tile (guarded)
    const int row0 = blockIdx.x * 128;
    for (int idx = tid; idx < 128 * 32; idx += 256) {
        int r = idx >> 5, c4 = idx & 31;
        float4 v = make_float4(0.f, 0.f, 0.f, 0.f);
        if (row0 + r < NN)
            v = reinterpret_cast<const float4*>(A)[(size_t)(row0 + r) * 32 + c4];
        *reinterpret_cast<float4*>(&Xs[r * 132 + c4 * 4]) = v;
    }
    __syncthreads();

    const int m_off = (warp >> 1) * 32;        // 0,32,64,96
    const int n_off = (warp & 1) * (OUT / 2);  // 0, OUT/2
    const int gid = lane >> 2;                 // group id 0..7
    const int tig = lane & 3;                  // thread in group 0..3

    float acc[2][NA][4];
    #pragma unroll
    for (int ma = 0; ma < 2; ma++)
        #pragma unroll
        for (int na = 0; na < NA; na++)
            #pragma unroll
            for (int c = 0; c < 4; c++) acc[ma][na][c] = 0.f;

    #pragma unroll 4
    for (int k0 = 0; k0 < 128; k0 += 8) {
        // A fragments (2 m-atoms), hi/lo
        uint32_t ah[2][4], al[2][4];
        #pragma unroll
        for (int ma = 0; ma < 2; ma++) {
            int rbase = m_off + ma * 16 + gid;
            #pragma unroll
            for (int q = 0; q < 4; q++) {
                int r = rbase + ((q & 1) ? 8 : 0);
                int k = k0 + tig + ((q & 2) ? 4 : 0);
                float v  = Xs[r * 132 + k];
                uint32_t h = f2tf32(v);
                float lo = v - __uint_as_float(h);
                ah[ma][q] = h;
                al[ma][q] = f2tf32(lo);
            }
        }
        // B fragments per n-atom, then 3 split MMAs x 2 m-atoms
        #pragma unroll
        for (int na = 0; na < NA; na++) {
            int n = n_off + na * 8 + gid;
            float v0 = Ws[n * 132 + k0 + tig];
            float v1 = Ws[n * 132 + k0 + tig + 4];
            uint32_t bh0 = f2tf32(v0), bh1 = f2tf32(v1);
            uint32_t bl0 = f2tf32(v0 - __uint_as_float(bh0));
            uint32_t bl1 = f2tf32(v1 - __uint_as_float(bh1));
            #pragma unroll
            for (int ma = 0; ma < 2; ma++) {
                float* d = acc[ma][na];
                mma_tf32(d[0], d[1], d[2], d[3],
                         al[ma][0], al[ma][1], al[ma][2], al[ma][3], bh0, bh1);
                mma_tf32(d[0], d[1], d[2], d[3],
                         ah[ma][0], ah[ma][1], ah[ma][2], ah[ma][3], bl0, bl1);
                mma_tf32(d[0], d[1], d[2], d[3],
                         ah[ma][0], ah[ma][1], ah[ma][2], ah[ma][3], bh0, bh1);
            }
        }
    }

    // epilogue
    #pragma unroll
    for (int ma = 0; ma < 2; ma++) {
        #pragma unroll
        for (int na = 0; na < NA; na++) {
            int col = n_off + na * 8 + 2 * tig;
            float bx = 0.f, by = 0.f;
            if (bias) { bx = __ldg(&bias[col]); by = __ldg(&bias[col + 1]); }
            int r0 = row0 + m_off + ma * 16 + gid;
            if (r0 < NN) {
                float2 v = make_float2(acc[ma][na][0] + bx, acc[ma][na][1] + by);
                *reinterpret_cast<float2*>(&C[(size_t)r0 * OUT + col]) = v;
            }
            int r1 = r0 + 8;
            if (r1 < NN) {
                float2 v = make_float2(acc[ma][na][2] + bx, acc[ma][na][3] + by);
                *reinterpret_cast<float2*>(&C[(size_t)r1 * OUT + col]) = v;
            }
        }
    }
}

// -------- aggregation + self-loop + bias + ReLU fused: warp per node -------
__global__ void k_agg_relu(const float* __restrict__ h,
                           const float* __restrict__ bias,
                           float* __restrict__ out)
{
    int gw = (blockIdx.x * blockDim.x + threadIdx.x) >> 5;   // node id
    if (gw >= NN) return;
    int lane = threadIdx.x & 31;
    int beg = g_rowstart[gw];
    int cnt = g_deg[gw];
    const float4* hp = reinterpret_cast<const float4*>(h);
    float4 acc0 = make_float4(0.f, 0.f, 0.f, 0.f);
    float4 acc1 = make_float4(0.f, 0.f, 0.f, 0.f);
    int t = 0;
    for (; t + 1 < cnt; t += 2) {
        int   s0 = __ldg(&g_csrc[beg + t]);
        int   s1 = __ldg(&g_csrc[beg + t + 1]);
        float n0 = __ldg(&g_cnorm[beg + t]);
        float n1 = __ldg(&g_cnorm[beg + t + 1]);
        float4 h0 = __ldg(&hp[(size_t)s0 * 32 + lane]);
        float4 h1 = __ldg(&hp[(size_t)s1 * 32 + lane]);
        acc0.x += n0 * h0.x; acc0.y += n0 * h0.y;
        acc0.z += n0 * h0.z; acc0.w += n0 * h0.w;
        acc1.x += n1 * h1.x; acc1.y += n1 * h1.y;
        acc1.z += n1 * h1.z; acc1.w += n1 * h1.w;
    }
    if (t < cnt) {
        int   s0 = __ldg(&g_csrc[beg + t]);
        float n0 = __ldg(&g_cnorm[beg + t]);
        float4 h0 = __ldg(&hp[(size_t)s0 * 32 + lane]);
        acc0.x += n0 * h0.x; acc0.y += n0 * h0.y;
        acc0.z += n0 * h0.z; acc0.w += n0 * h0.w;
    }
    float di = g_dinv[gw];
    float c  = di * di;                               // self-loop norm
    float4 hs = __ldg(&hp[(size_t)gw * 32 + lane]);
    float4 b  = __ldg(&reinterpret_cast<const float4*>(bias)[lane]);
    float4 r;
    r.x = fmaxf(acc0.x + acc1.x + c * hs.x + b.x, 0.f);
    r.y = fmaxf(acc0.y + acc1.y + c * hs.y + b.y, 0.f);
    r.z = fmaxf(acc0.z + acc1.z + c * hs.z + b.z, 0.f);
    r.w = fmaxf(acc0.w + acc1.w + c * hs.w + b.w, 0.f);
    reinterpret_cast<float4*>(out)[(size_t)gw * 32 + lane] = r;
}

// ---------------- launcher --------------------------------------------------
extern "C" void kernel_launch(void* const* d_in, const int* in_sizes, int n_in,
                              void* d_out, int out_size)
{
    (void)in_sizes; (void)n_in; (void)out_size;
    const float* x  = (const float*)d_in[0];
    const int*   ei = (const int*)d_in[1];          // int32 (JAX x64 disabled)
    const float* W1 = (const float*)d_in[2];
    const float* b1 = (const float*)d_in[3];
    const float* W2 = (const float*)d_in[4];
    const float* b2 = (const float*)d_in[5];
    const float* Wl = (const float*)d_in[6];
    const float* bl = (const float*)d_in[7];
    float* out = (float*)d_out;

    void *pb1, *pb3;
    cudaGetSymbolAddress(&pb1, g_buf1);
    cudaGetSymbolAddress(&pb3, g_buf3);
    float* buf1 = (float*)pb1;
    float* buf3 = (float*)pb3;

    const int SMEM128 = (128 * 132 + 128 * 132) * 4;   // 135168 B
    const int SMEM64  = (128 * 132 + 64 * 132) * 4;    // 101376 B
    cudaFuncSetAttribute(k_gemm<128>, cudaFuncAttributeMaxDynamicSharedMemorySize, SMEM128);
    cudaFuncSetAttribute(k_gemm<64>,  cudaFuncAttributeMaxDynamicSharedMemorySize, SMEM64);

    const int TB = 256;
    const int GB_N  = (NN + TB - 1) / TB;          // 391
    const int GB_E  = (NE + TB - 1) / TB;          // 6250
    const int GB_W  = (NN * 32 + TB - 1) / TB;     // 12500 (warp per node)
    const int GB_MM = (NN + 127) / 128;            // 782

    // --- graph preprocessing (recomputed every call) ---
    k_init<<<GB_N, TB>>>();
    k_count<<<GB_E, TB>>>(ei);
    k_scan_blocks<<<NB_SCAN, 1024>>>();
    k_scan_top<<<1, 128>>>();
    k_finish<<<GB_N, TB>>>();
    k_fill<<<GB_E, TB>>>(ei);

    // --- layer 1 ---
    k_gemm<128><<<GB_MM, TB, SMEM128>>>(x, W1, nullptr, buf1);
    k_agg_relu<<<GB_W, TB>>>(buf1, b1, buf3);

    // --- layer 2 ---
    k_gemm<128><<<GB_MM, TB, SMEM128>>>(buf3, W2, nullptr, buf1);
    k_agg_relu<<<GB_W, TB>>>(buf1, b2, buf3);

    // --- readout ---
    k_gemm<64><<<GB_MM, TB, SMEM64>>>(buf3, Wl, bl, out);
}